// round 1
// baseline (speedup 1.0000x reference)
#include <cuda_runtime.h>

// 3x3 stride-1 pad-1 conv2d, fp32, B=16, Cin=Cout=64, H=W=256.
// Direct conv, smem-tiled, packed fma.rn.f32x2 over adjacent C_out pairs.

constexpr int C_INC  = 64;
constexpr int C_OUTC = 64;
constexpr int HH = 256;
constexpr int WW = 256;
constexpr int TH = 8;     // output rows per CTA
constexpr int TW = 32;    // output cols per CTA
constexpr int CIT = 8;    // C_in chunk held in smem
constexpr int XSTRIDE = TW + 3;  // 35: odd pad -> conflict-free LDS across rows

__device__ __forceinline__ unsigned long long dup2(float v) {
    unsigned long long r;
    asm("mov.b64 %0, {%1,%1};" : "=l"(r) : "f"(v));
    return r;
}
__device__ __forceinline__ unsigned long long fma2(unsigned long long a,
                                                   unsigned long long b,
                                                   unsigned long long c) {
    unsigned long long d;
    asm("fma.rn.f32x2 %0, %1, %2, %3;" : "=l"(d) : "l"(a), "l"(b), "l"(c));
    return d;
}
__device__ __forceinline__ void unpack2(unsigned long long v, float& lo, float& hi) {
    asm("mov.b64 {%0,%1}, %2;" : "=f"(lo), "=f"(hi) : "l"(v));
}

__global__ __launch_bounds__(256, 2)
void conv3x3_f32x2_kernel(const float* __restrict__ x,
                          const float* __restrict__ wgt,
                          const float* __restrict__ bias,
                          float* __restrict__ out)
{
    __shared__ float sx[CIT][TH + 2][XSTRIDE];   // input tile w/ halo
    __shared__ float sw[CIT][9][C_OUTC];         // weights, co contiguous

    const int tid = threadIdx.x;
    const int b   = blockIdx.z;
    const int y0  = blockIdx.y * TH;
    const int x0  = blockIdx.x * TW;

    const int cog    = tid >> 6;          // 0..3 : which 16-cout group
    const int pix    = tid & 63;          // 0..63
    const int py     = pix >> 3;          // 0..7  : row in tile
    const int pxc    = (pix & 7) << 2;    // 0,4,...,28 : col base (4 pixels)
    const int cobase = cog * 16;

    // acc[cg][j]: f32x2 pair (co = cobase+2cg, cobase+2cg+1), pixel x0+pxc+j
    unsigned long long acc[8][4];
    #pragma unroll
    for (int i = 0; i < 8; i++)
        #pragma unroll
        for (int j = 0; j < 4; j++)
            acc[i][j] = 0ull;

    const float* xb = x + (size_t)b * C_INC * (HH * WW);

    for (int ci0 = 0; ci0 < C_INC; ci0 += CIT) {
        __syncthreads();
        // ---- stage x tile (with zero halo) ----
        for (int i = tid; i < CIT * (TH + 2) * (TW + 2); i += 256) {
            int ci  = i / ((TH + 2) * (TW + 2));
            int rem = i % ((TH + 2) * (TW + 2));
            int r = rem / (TW + 2);
            int c = rem % (TW + 2);
            int gy = y0 - 1 + r;
            int gx = x0 - 1 + c;
            float v = 0.0f;
            if ((unsigned)gy < (unsigned)HH && (unsigned)gx < (unsigned)WW)
                v = xb[(size_t)(ci0 + ci) * (HH * WW) + gy * WW + gx];
            sx[ci][r][c] = v;
        }
        // ---- stage weights: sw[ci][k][co] = wgt[co][ci0+ci][k] ----
        for (int i = tid; i < CIT * 9 * C_OUTC; i += 256) {
            int co = i & 63;
            int k  = (i >> 6) % 9;
            int ci = i / (9 * 64);
            sw[ci][k][co] = wgt[(co * C_INC + ci0 + ci) * 9 + k];
        }
        __syncthreads();

        #pragma unroll 1
        for (int ci = 0; ci < CIT; ci++) {
            #pragma unroll
            for (int kh = 0; kh < 3; kh++) {
                const float* xr = &sx[ci][py + kh][pxc];
                unsigned long long xd[6];
                #pragma unroll
                for (int m = 0; m < 6; m++) xd[m] = dup2(xr[m]);

                // sw[ci][kh*3 + kw][cobase + 2cg] ; kw rows are 64 floats = 32 ull apart
                const unsigned long long* wr =
                    (const unsigned long long*)(&sw[ci][kh * 3][cobase]);
                #pragma unroll
                for (int cg = 0; cg < 8; cg++) {
                    unsigned long long w0 = wr[cg];        // kw=0, broadcast LDS.64
                    unsigned long long w1 = wr[32 + cg];   // kw=1
                    unsigned long long w2 = wr[64 + cg];   // kw=2
                    #pragma unroll
                    for (int j = 0; j < 4; j++) {
                        acc[cg][j] = fma2(w0, xd[j],     acc[cg][j]);
                        acc[cg][j] = fma2(w1, xd[j + 1], acc[cg][j]);
                        acc[cg][j] = fma2(w2, xd[j + 2], acc[cg][j]);
                    }
                }
            }
        }
    }

    // ---- epilogue: add bias, write 4-wide float4 per cout ----
    const int oy = y0 + py;
    const int ox = x0 + pxc;
    #pragma unroll
    for (int cg = 0; cg < 8; cg++) {
        int co0 = cobase + 2 * cg;
        float b0 = bias[co0], b1 = bias[co0 + 1];
        float4 v0, v1;
        float lo, hi;
        unpack2(acc[cg][0], lo, hi); v0.x = lo + b0; v1.x = hi + b1;
        unpack2(acc[cg][1], lo, hi); v0.y = lo + b0; v1.y = hi + b1;
        unpack2(acc[cg][2], lo, hi); v0.z = lo + b0; v1.z = hi + b1;
        unpack2(acc[cg][3], lo, hi); v0.w = lo + b0; v1.w = hi + b1;
        size_t base0 = (((size_t)b * C_OUTC + co0) * HH + oy) * (size_t)WW + ox;
        *(float4*)(out + base0) = v0;
        *(float4*)(out + base0 + (size_t)HH * WW) = v1;
    }
}

extern "C" void kernel_launch(void* const* d_in, const int* in_sizes, int n_in,
                              void* d_out, int out_size)
{
    const float* x    = (const float*)d_in[0];
    const float* wgt  = (const float*)d_in[1];
    const float* bias = (const float*)d_in[2];
    float* out        = (float*)d_out;

    dim3 grid(WW / TW, HH / TH, 16);   // (8, 32, 16) = 4096 CTAs
    conv3x3_f32x2_kernel<<<grid, 256>>>(x, wgt, bias, out);
}